// round 8
// baseline (speedup 1.0000x reference)
#include <cuda_runtime.h>
#include <math.h>
#include <stddef.h>

// Problem constants (B=1)
#define S_LEN  4096
#define DMODEL 512
#define IN_DIM 512
#define NHEAD  8
#define DKH    64          // head dim

// ---------------- scratch (device globals; no allocations allowed) ----------
__device__ float g_Q[S_LEN * DMODEL];
__device__ float g_K[S_LEN * DMODEL];
__device__ float g_V[S_LEN * DMODEL];
__device__ float g_AO[S_LEN * DMODEL];
__device__ unsigned long long g_MB[S_LEN * (S_LEN / 64)];   // bit-packed mask

// ---------------- helpers ----------------------------------------------------
__device__ __forceinline__ unsigned f2tf32(float x) {
    unsigned u;
    asm("cvt.rna.tf32.f32 %0, %1;" : "=r"(u) : "f"(x));
    return u;
}
__device__ __forceinline__ float f2tf32f(float x) {
    return __uint_as_float(f2tf32(x));
}
__device__ __forceinline__ float ex2f(float x) {
    float y;
    asm("ex2.approx.ftz.f32 %0, %1;" : "=f"(y) : "f"(x));
    return y;
}
__device__ __forceinline__ void cpa16(unsigned dst_smem, const void* src) {
    asm volatile("cp.async.cg.shared.global [%0], [%1], 16;\n"
                 :: "r"(dst_smem), "l"(src));
}
#define CP_COMMIT() asm volatile("cp.async.commit_group;\n" ::: "memory")
#define CP_WAIT0()  asm volatile("cp.async.wait_group 0;\n" ::: "memory")
#define CP_WAIT1()  asm volatile("cp.async.wait_group 1;\n" ::: "memory")

__device__ __forceinline__ void ldsm_x4(unsigned addr,
    unsigned& r0, unsigned& r1, unsigned& r2, unsigned& r3)
{
    asm volatile("ldmatrix.sync.aligned.m8n8.x4.shared.b16 {%0,%1,%2,%3}, [%4];\n"
                 : "=r"(r0), "=r"(r1), "=r"(r2), "=r"(r3) : "r"(addr));
}

__device__ __forceinline__ void mma_tf32(float c[4],
    unsigned a0, unsigned a1, unsigned a2, unsigned a3,
    unsigned b0, unsigned b1)
{
    asm volatile(
        "mma.sync.aligned.m16n8k8.row.col.f32.tf32.tf32.f32 "
        "{%0,%1,%2,%3}, {%4,%5,%6,%7}, {%8,%9}, {%0,%1,%2,%3};\n"
        : "+f"(c[0]), "+f"(c[1]), "+f"(c[2]), "+f"(c[3])
        : "r"(a0), "r"(a1), "r"(a2), "r"(a3), "r"(b0), "r"(b1));
}

// ============================================================================
// Mask bit-pack: one warp per output uint64 (64 mask columns).
// ============================================================================
__global__ __launch_bounds__(256) void pack_mask_kernel(
    const int* __restrict__ mask, unsigned long long* __restrict__ packed)
{
    const int wid  = (blockIdx.x * blockDim.x + threadIdx.x) >> 5;
    const int lane = threadIdx.x & 31;
    const int row  = wid >> 6;
    const int word = wid & 63;
    const int* p = mask + (size_t)row * S_LEN + word * 64;
    unsigned lo = __ballot_sync(0xffffffffu, p[lane]      != 0);
    unsigned hi = __ballot_sync(0xffffffffu, p[lane + 32] != 0);
    if (lane == 0)
        packed[wid] = ((unsigned long long)hi << 32) | (unsigned long long)lo;
}

// ============================================================================
// tf32 GEMM, 3-stage cp.async pipeline, tf32-by-truncation:
// C[m0:+128, n0:+128] = A[M,K]*B[N,K]^T + bias. 8 warps (4M x 2N), 32x64/warp.
// ============================================================================
#define TGK 16
#define LA  20
#define ABUF (128 * LA)
#define GEMM_SMEM_BYTES (3 * 2 * ABUF * 4)

__device__ __forceinline__ void gemm_tf32_body(
    const float* __restrict__ A, const float* __restrict__ B,
    const float* __restrict__ bias, float* __restrict__ C,
    int K, int ldc, int m0, int n0, float* smbase)
{
    float* Asb = smbase;                 // 3 stages of A
    float* Bsb = smbase + 3 * ABUF;      // 3 stages of B

    const int tid  = threadIdx.x;
    const int w    = tid >> 5, lane = tid & 31;
    const int g    = lane >> 2, tig = lane & 3;
    const int wm   = w & 3, wn = w >> 2;
    const int r    = tid >> 2;                 // 0..63
    const int cg   = (tid & 3) * 4;            // 0,4,8,12

    const unsigned sA = (unsigned)__cvta_generic_to_shared(Asb);
    const unsigned sB = (unsigned)__cvta_generic_to_shared(Bsb);

    float c[2][8][4];
#pragma unroll
    for (int mt = 0; mt < 2; mt++)
#pragma unroll
        for (int nt = 0; nt < 8; nt++)
#pragma unroll
            for (int j = 0; j < 4; j++) c[mt][nt][j] = 0.f;

    const int nsteps = K / TGK;

    auto issue = [&](int step, int st) {
        const int k0 = step * TGK;
        const unsigned a_dst = sA + (unsigned)(st * ABUF + r * LA + cg) * 4u;
        const unsigned b_dst = sB + (unsigned)(st * ABUF + r * LA + cg) * 4u;
        cpa16(a_dst,                            A + (size_t)(m0 + r)      * K + k0 + cg);
        cpa16(a_dst + (unsigned)(64 * LA) * 4u, A + (size_t)(m0 + r + 64) * K + k0 + cg);
        cpa16(b_dst,                            B + (size_t)(n0 + r)      * K + k0 + cg);
        cpa16(b_dst + (unsigned)(64 * LA) * 4u, B + (size_t)(n0 + r + 64) * K + k0 + cg);
    };

    issue(0, 0); CP_COMMIT();
    issue(1, 1); CP_COMMIT();

    for (int i = 0; i < nsteps; i++) {
        CP_WAIT1();
        __syncthreads();
        if (i + 2 < nsteps) issue(i + 2, (i + 2) % 3);
        CP_COMMIT();

        const float* As = Asb + (i % 3) * ABUF;
        const float* Bs = Bsb + (i % 3) * ABUF;

#pragma unroll
        for (int kk = 0; kk < 2; kk++) {
            unsigned af[2][4];
#pragma unroll
            for (int mt = 0; mt < 2; mt++) {
                const int row = wm * 32 + mt * 16;
                af[mt][0] = __float_as_uint(As[(row + g)     * LA + kk * 8 + tig]);
                af[mt][1] = __float_as_uint(As[(row + g + 8) * LA + kk * 8 + tig]);
                af[mt][2] = __float_as_uint(As[(row + g)     * LA + kk * 8 + tig + 4]);
                af[mt][3] = __float_as_uint(As[(row + g + 8) * LA + kk * 8 + tig + 4]);
            }
#pragma unroll
            for (int nt = 0; nt < 8; nt++) {
                const int brow = wn * 64 + nt * 8 + g;
                unsigned bf0 = __float_as_uint(Bs[brow * LA + kk * 8 + tig]);
                unsigned bf1 = __float_as_uint(Bs[brow * LA + kk * 8 + tig + 4]);
                mma_tf32(c[0][nt], af[0][0], af[0][1], af[0][2], af[0][3], bf0, bf1);
                mma_tf32(c[1][nt], af[1][0], af[1][1], af[1][2], af[1][3], bf0, bf1);
            }
        }
    }

#pragma unroll
    for (int nt = 0; nt < 8; nt++) {
        const int col = n0 + wn * 64 + nt * 8 + 2 * tig;
        const float2 bv = *(const float2*)(bias + col);
#pragma unroll
        for (int mt = 0; mt < 2; mt++) {
            const int row = m0 + wm * 32 + mt * 16 + g;
            *(float2*)(C + (size_t)row * ldc + col) =
                make_float2(c[mt][nt][0] + bv.x, c[mt][nt][1] + bv.y);
            *(float2*)(C + (size_t)(row + 8) * ldc + col) =
                make_float2(c[mt][nt][2] + bv.x, c[mt][nt][3] + bv.y);
        }
    }
}

__global__ __launch_bounds__(256, 2) void qkv_gemm_kernel(
    const float* __restrict__ x,
    const float* __restrict__ wq, const float* __restrict__ bq,
    const float* __restrict__ wk, const float* __restrict__ bk,
    const float* __restrict__ wv, const float* __restrict__ bv,
    float* __restrict__ Qo, float* __restrict__ Ko, float* __restrict__ Vo)
{
    extern __shared__ float sm[];
    const int nb  = blockIdx.x;          // 0..11
    const int mat = nb >> 2;             // 0:Q 1:K 2:V
    const int n0  = (nb & 3) * 128;
    const int m0  = blockIdx.y * 128;
    const float* B    = (mat == 0) ? wq : (mat == 1) ? wk : wv;
    const float* bias = (mat == 0) ? bq : (mat == 1) ? bk : bv;
    float* C          = (mat == 0) ? Qo : (mat == 1) ? Ko : Vo;
    gemm_tf32_body(x, B, bias, C, IN_DIM, DMODEL, m0, n0, sm);
}

__global__ __launch_bounds__(256, 2) void dense_gemm_kernel(
    const float* __restrict__ A, const float* __restrict__ B,
    const float* __restrict__ bias, float* __restrict__ C)
{
    extern __shared__ float sm[];
    gemm_tf32_body(A, B, bias, C, DMODEL, DMODEL,
                   blockIdx.y * 128, blockIdx.x * 128, sm);
}

// ============================================================================
// Flash attention v7: split-KV warp pairs, V in natural [token][dim] layout
// (R4-proven scalar V b-frags, LV=72 conflict-free). 512 threads, BQ=128,
// grid (32, 8). Warps w (sel=0) and w+8 (sel=1) share q-rows [(w&7)*16,+16);
// each handles 32 of the 64 KV tokens/chunk, independent online softmax,
// merged once at the end. K and P fragments via ldmatrix.x4.
// ============================================================================
#define BQ   128
#define BKC  64
#define LQ   68
#define LK   68
#define LV   72
#define LOS  66
#define KBUF (BKC * LK)
#define VBUF (BKC * LV)

#define ATTN_SMEM_FLOATS (BQ * LQ + 2 * KBUF + 2 * VBUF)
#define ATTN_SMEM_BYTES  (ATTN_SMEM_FLOATS * 4)

#define SCALE2 0.1803368801f   // 0.125 * log2(e)

__global__ __launch_bounds__(512, 1) void attn_tc_kernel(
    const float* __restrict__ Q, const float* __restrict__ K,
    const float* __restrict__ V, const unsigned long long* __restrict__ mbits,
    float* __restrict__ O)
{
    extern __shared__ float sm[];
    float* QPs = sm;                       // [BQ][LQ] : Q, then P
    float* Ks  = sm + BQ * LQ;             // 2 x [64 tok][LK]
    float* Vs  = Ks + 2 * KBUF;            // 2 x [64 tok][LV]

    const unsigned sQP = (unsigned)__cvta_generic_to_shared(QPs);
    const unsigned sK  = (unsigned)__cvta_generic_to_shared(Ks);
    const unsigned sV  = (unsigned)__cvta_generic_to_shared(Vs);

    const int tid  = threadIdx.x;
    const int w    = tid >> 5;            // 0..15
    const int lane = tid & 31;
    const int g    = lane >> 2;
    const int tig  = lane & 3;
    const int lrow = lane & 7;
    const int lm   = lane >> 3;
    const int h    = blockIdx.y;
    const int qb   = blockIdx.x;
    const int rg   = w & 7;               // q-row group
    const int sel  = w >> 3;              // KV half
    const int rb   = rg * 16;             // row base within tile

    const float* Qg = Q + ((size_t)h * S_LEN + (size_t)qb * BQ) * DKH;
    const float* Kg = K + (size_t)h * S_LEN * DKH;
    const float* Vg = V + (size_t)h * S_LEN * DKH;

    // copy slice: 4 float4 per thread. tid<256 -> K, else V.
    // 256 threads cover 64 rows x 64 floats: 4 threads/row, 4 float4 each.
    const int cvsel = tid >> 8;
    const int r8    = (tid & 255) >> 2;   // 0..63
    const int c16   = (tid & 3) * 16;     // float column base 0,16,32,48

    auto issue_kv = [&](int kb, int bb) {
#pragma unroll
        for (int p = 0; p < 4; p++) {
            const int c = c16 + p * 4;
            if (cvsel == 0)
                cpa16(sK + (unsigned)(bb * KBUF + r8 * LK + c) * 4u,
                      Kg + (size_t)(kb * BKC + r8) * DKH + c);
            else
                cpa16(sV + (unsigned)(bb * VBUF + r8 * LV + c) * 4u,
                      Vg + (size_t)(kb * BKC + r8) * DKH + c);
        }
    };

    // ---- prologue: Q tile (128x64) + chunk 0 ----
#pragma unroll
    for (int p = 0; p < 4; p++) {
        const int f   = tid + p * 512;
        const int row = f >> 4;
        const int col = (f & 15) * 4;
        cpa16(sQP + (unsigned)(row * LQ + col) * 4u, Qg + (size_t)row * DKH + col);
    }
    issue_kv(0, 0);
    CP_COMMIT();
    CP_WAIT0();
    __syncthreads();

    // hoist Q fragments (RN tf32); frees QPs for P reuse
    unsigned qa[8][4];
#pragma unroll
    for (int kk = 0; kk < 8; kk++) {
        qa[kk][0] = f2tf32(QPs[(rb + g)     * LQ + kk * 8 + tig]);
        qa[kk][1] = f2tf32(QPs[(rb + g + 8) * LQ + kk * 8 + tig]);
        qa[kk][2] = f2tf32(QPs[(rb + g)     * LQ + kk * 8 + tig + 4]);
        qa[kk][3] = f2tf32(QPs[(rb + g + 8) * LQ + kk * 8 + tig + 4]);
    }

    float m0 = -INFINITY, m1 = -INFINITY, l0 = 0.f, l1 = 0.f;
    float o[8][4];
#pragma unroll
    for (int nt = 0; nt < 8; nt++)
#pragma unroll
        for (int j = 0; j < 4; j++) o[nt][j] = 0.f;

    const int row0 = qb * BQ + rb + g;
    const int row1 = row0 + 8;
    const unsigned long long* mb0p = mbits + (size_t)row0 * 64;
    const unsigned long long* mb1p = mbits + (size_t)row1 * 64;
    const int mshift = sel * 32 + 2 * tig;

    const unsigned klane = (unsigned)(lrow * LK + lm * 4) * 4u;
    const unsigned pbase = sQP +
        (unsigned)((rb + (lm & 1) * 8 + lrow) * LQ + sel * 32 + (lm >> 1) * 4) * 4u;

    for (int kb = 0; kb < S_LEN / BKC; kb++) {
        CP_WAIT0();
        __syncthreads();

        const unsigned long long b0 = mb0p[kb] >> mshift;
        const unsigned long long b1 = mb1p[kb] >> mshift;

        if (kb + 1 < S_LEN / BKC) issue_kv(kb + 1, (kb + 1) & 1);
        CP_COMMIT();

        const unsigned kbase = sK + (unsigned)((kb & 1) * KBUF) * 4u + klane;
        const float*   Vb    = Vs + (kb & 1) * VBUF;

        // ---- S = Q * K^T over this warp's 32 tokens (4 n-tiles) ----
        float s[4][4];
#pragma unroll
        for (int nt = 0; nt < 4; nt++) {
#pragma unroll
            for (int j = 0; j < 4; j++) s[nt][j] = 0.f;
            const unsigned bnt = kbase + (unsigned)((sel * 32 + nt * 8) * LK) * 4u;
#pragma unroll
            for (int p = 0; p < 4; p++) {
                unsigned r0, r1, r2, r3;
                ldsm_x4(bnt + (unsigned)(p * 16) * 4u, r0, r1, r2, r3);
                mma_tf32(s[nt], qa[2*p][0], qa[2*p][1], qa[2*p][2], qa[2*p][3], r0, r1);
                mma_tf32(s[nt], qa[2*p+1][0], qa[2*p+1][1], qa[2*p+1][2], qa[2*p+1][3], r2, r3);
            }
        }

        // ---- mask + online softmax (exp2 domain), 32-token half ----
        float mx0 = -INFINITY, mx1 = -INFINITY;
#pragma unroll
        for (int nt = 0; nt < 4; nt++) {
            s[nt][0] = fmaf(s[nt][0], SCALE2, ((b0 >> (nt * 8    )) & 1ull) ? -1e9f : 0.f);
            s[nt][1] = fmaf(s[nt][1], SCALE2, ((b0 >> (nt * 8 + 1)) & 1ull) ? -1e9f : 0.f);
            s[nt][2] = fmaf(s[nt][2], SCALE2, ((b1 >> (nt * 8    )) & 1ull) ? -1e9f : 0.f);
            s[nt][3] = fmaf(s[nt][3], SCALE2, ((b1 >> (nt * 8 + 1)) & 1ull) ? -1e9f : 0.f);
            mx0 = fmaxf(mx0, fmaxf(s[nt][0], s[nt][1]));
            mx1 = fmaxf(mx1, fmaxf(s[nt][2], s[nt][3]));
        }
        mx0 = fmaxf(mx0, __shfl_xor_sync(0xffffffffu, mx0, 1));
        mx0 = fmaxf(mx0, __shfl_xor_sync(0xffffffffu, mx0, 2));
        mx1 = fmaxf(mx1, __shfl_xor_sync(0xffffffffu, mx1, 1));
        mx1 = fmaxf(mx1, __shfl_xor_sync(0xffffffffu, mx1, 2));

        const float mn0 = fmaxf(m0, mx0), mn1 = fmaxf(m1, mx1);
        const float sc0 = ex2f(m0 - mn0), sc1 = ex2f(m1 - mn1);
        m0 = mn0; m1 = mn1;

        float rs0 = 0.f, rs1 = 0.f;
#pragma unroll
        for (int nt = 0; nt < 4; nt++) {
            const float p0 = ex2f(s[nt][0] - mn0);
            const float p1 = ex2f(s[nt][1] - mn0);
            const float p2 = ex2f(s[nt][2] - mn1);
            const float p3 = ex2f(s[nt][3] - mn1);
            rs0 += p0 + p1;
            rs1 += p2 + p3;
            *(float2*)&QPs[(rb + g)     * LQ + sel * 32 + nt * 8 + 2 * tig] =
                make_float2(f2tf32f(p0), f2tf32f(p1));
            *(float2*)&QPs[(rb + g + 8) * LQ + sel * 32 + nt * 8 + 2 * tig] =
                make_float2(f2tf32f(p2), f2tf32f(p3));
        }
        rs0 += __shfl_xor_sync(0xffffffffu, rs0, 1);
        rs0 += __shfl_xor_sync(0xffffffffu, rs0, 2);
        rs1 += __shfl_xor_sync(0xffffffffu, rs1, 1);
        rs1 += __shfl_xor_sync(0xffffffffu, rs1, 2);
        l0 = l0 * sc0 + rs0;
        l1 = l1 * sc1 + rs1;
#pragma unroll
        for (int nt = 0; nt < 8; nt++) {
            o[nt][0] *= sc0; o[nt][1] *= sc0;
            o[nt][2] *= sc1; o[nt][3] *= sc1;
        }

        __syncwarp();   // P visible within warp (exclusive row+col ownership)

        // ---- O += P * V : P a-frags via ldmatrix, V scalar (LV=72, no conflicts)
        unsigned pa[4][4];
#pragma unroll
        for (int kc = 0; kc < 4; kc++)
            ldsm_x4(pbase + (unsigned)(kc * 8) * 4u,
                    pa[kc][0], pa[kc][1], pa[kc][2], pa[kc][3]);

#pragma unroll
        for (int kc = 0; kc < 4; kc++) {
            const float* vr0 = Vb + (sel * 32 + kc * 8 + tig)     * LV + g;
            const float* vr1 = Vb + (sel * 32 + kc * 8 + tig + 4) * LV + g;
#pragma unroll
            for (int nt = 0; nt < 8; nt++) {
                unsigned bb0 = __float_as_uint(vr0[nt * 8]);
                unsigned bb1 = __float_as_uint(vr1[nt * 8]);
                mma_tf32(o[nt], pa[kc][0], pa[kc][1], pa[kc][2], pa[kc][3], bb0, bb1);
            }
        }
    }

    // ---- final split-softmax merge between warp pairs ----
    float* Os = Ks;                       // 128 x LOS (fits in K region)
    float* Ms = Vs;                       // 128 x 2
    const int r0l = rb + g;
    const int r1l = r0l + 8;

    __syncthreads();
    if (sel == 1) {
#pragma unroll
        for (int nt = 0; nt < 8; nt++) {
            *(float2*)&Os[r0l * LOS + nt * 8 + 2 * tig] = make_float2(o[nt][0], o[nt][1]);
            *(float2*)&Os[r1l * LOS + nt * 8 + 2 * tig] = make_float2(o[nt][2], o[nt][3]);
        }
        if (tig == 0) {
            Ms[r0l * 2] = m0; Ms[r0l * 2 + 1] = l0;
            Ms[r1l * 2] = m1; Ms[r1l * 2 + 1] = l1;
        }
    }
    __syncthreads();

    if (sel == 0) {
        const float mp0 = Ms[r0l * 2], lp0 = Ms[r0l * 2 + 1];
        const float mp1 = Ms[r1l * 2], lp1 = Ms[r1l * 2 + 1];
        const float M0 = fmaxf(m0, mp0), M1 = fmaxf(m1, mp1);
        const float f0 = ex2f(m0 - M0), fp0 = ex2f(mp0 - M0);
        const float f1 = ex2f(m1 - M1), fp1 = ex2f(mp1 - M1);
        const float inv0 = 1.0f / (l0 * f0 + lp0 * fp0);
        const float inv1 = 1.0f / (l1 * f1 + lp1 * fp1);
        float* O0 = O + (size_t)row0 * DMODEL + h * DKH + 2 * tig;
        float* O1 = O + (size_t)row1 * DMODEL + h * DKH + 2 * tig;
#pragma unroll
        for (int nt = 0; nt < 8; nt++) {
            const float2 p0 = *(const float2*)&Os[r0l * LOS + nt * 8 + 2 * tig];
            const float2 p1 = *(const float2*)&Os[r1l * LOS + nt * 8 + 2 * tig];
            *(float2*)(O0 + nt * 8) = make_float2(
                (o[nt][0] * f0 + p0.x * fp0) * inv0,
                (o[nt][1] * f0 + p0.y * fp0) * inv0);
            *(float2*)(O1 + nt * 8) = make_float2(
                (o[nt][2] * f1 + p1.x * fp1) * inv1,
                (o[nt][3] * f1 + p1.y * fp1) * inv1);
        }
    }
}

// ============================================================================
extern "C" void kernel_launch(void* const* d_in, const int* in_sizes, int n_in,
                              void* d_out, int out_size)
{
    const float* x       = (const float*)d_in[0];
    const int*   mask    = (const int*)  d_in[1];
    const float* wq_w    = (const float*)d_in[2];
    const float* wq_b    = (const float*)d_in[3];
    const float* wk_w    = (const float*)d_in[4];
    const float* wk_b    = (const float*)d_in[5];
    const float* wv_w    = (const float*)d_in[6];
    const float* wv_b    = (const float*)d_in[7];
    const float* dense_w = (const float*)d_in[8];
    const float* dense_b = (const float*)d_in[9];
    float* out = (float*)d_out;

    float *Qp, *Kp, *Vp, *AOp;
    unsigned long long* MBp;
    cudaGetSymbolAddress((void**)&Qp,  g_Q);
    cudaGetSymbolAddress((void**)&Kp,  g_K);
    cudaGetSymbolAddress((void**)&Vp,  g_V);
    cudaGetSymbolAddress((void**)&AOp, g_AO);
    cudaGetSymbolAddress((void**)&MBp, g_MB);

    cudaFuncSetAttribute(attn_tc_kernel,
                         cudaFuncAttributeMaxDynamicSharedMemorySize,
                         ATTN_SMEM_BYTES);
    cudaFuncSetAttribute(qkv_gemm_kernel,
                         cudaFuncAttributeMaxDynamicSharedMemorySize,
                         GEMM_SMEM_BYTES);
    cudaFuncSetAttribute(dense_gemm_kernel,
                         cudaFuncAttributeMaxDynamicSharedMemorySize,
                         GEMM_SMEM_BYTES);

    // 0) Bit-pack the mask
    pack_mask_kernel<<<(S_LEN * 64 * 32) / 256, 256>>>(mask, MBp);

    // 1) Fused QKV projections (3-stage cp.async tf32 GEMM)
    qkv_gemm_kernel<<<dim3(12, S_LEN / 128), 256, GEMM_SMEM_BYTES>>>(
        x, wq_w, wq_b, wk_w, wk_b, wv_w, wv_b, Qp, Kp, Vp);

    // 2) Split-KV masked flash attention
    attn_tc_kernel<<<dim3(S_LEN / BQ, NHEAD), 512, ATTN_SMEM_BYTES>>>(
        Qp, Kp, Vp, MBp, AOp);

    // 3) Dense output projection
    dense_gemm_kernel<<<dim3(DMODEL / 128, S_LEN / 128), 256, GEMM_SMEM_BYTES>>>(
        AOp, dense_w, dense_b, out);
}

// round 9
// speedup vs baseline: 1.3071x; 1.3071x over previous
#include <cuda_runtime.h>
#include <math.h>
#include <stddef.h>

// Problem constants (B=1)
#define S_LEN  4096
#define DMODEL 512
#define IN_DIM 512
#define NHEAD  8
#define DKH    64          // head dim

// ---------------- scratch (device globals; no allocations allowed) ----------
__device__ float g_Q[S_LEN * DMODEL];
__device__ float g_K[S_LEN * DMODEL];
__device__ float g_V[S_LEN * DMODEL];
__device__ float g_AO[S_LEN * DMODEL];
__device__ unsigned long long g_MB[S_LEN * (S_LEN / 64)];   // bit-packed mask

// ---------------- helpers ----------------------------------------------------
__device__ __forceinline__ unsigned f2tf32(float x) {
    unsigned u;
    asm("cvt.rna.tf32.f32 %0, %1;" : "=r"(u) : "f"(x));
    return u;
}
__device__ __forceinline__ float f2tf32f(float x) {
    return __uint_as_float(f2tf32(x));
}
__device__ __forceinline__ float ex2f(float x) {
    float y;
    asm("ex2.approx.ftz.f32 %0, %1;" : "=f"(y) : "f"(x));
    return y;
}
__device__ __forceinline__ void cpa16(unsigned dst_smem, const void* src) {
    asm volatile("cp.async.cg.shared.global [%0], [%1], 16;\n"
                 :: "r"(dst_smem), "l"(src));
}
#define CP_COMMIT() asm volatile("cp.async.commit_group;\n" ::: "memory")
#define CP_WAIT0()  asm volatile("cp.async.wait_group 0;\n" ::: "memory")
#define CP_WAIT1()  asm volatile("cp.async.wait_group 1;\n" ::: "memory")

__device__ __forceinline__ void ldsm_x4(unsigned addr,
    unsigned& r0, unsigned& r1, unsigned& r2, unsigned& r3)
{
    asm volatile("ldmatrix.sync.aligned.m8n8.x4.shared.b16 {%0,%1,%2,%3}, [%4];\n"
                 : "=r"(r0), "=r"(r1), "=r"(r2), "=r"(r3) : "r"(addr));
}

__device__ __forceinline__ void mma_tf32(float c[4],
    unsigned a0, unsigned a1, unsigned a2, unsigned a3,
    unsigned b0, unsigned b1)
{
    asm volatile(
        "mma.sync.aligned.m16n8k8.row.col.f32.tf32.tf32.f32 "
        "{%0,%1,%2,%3}, {%4,%5,%6,%7}, {%8,%9}, {%0,%1,%2,%3};\n"
        : "+f"(c[0]), "+f"(c[1]), "+f"(c[2]), "+f"(c[3])
        : "r"(a0), "r"(a1), "r"(a2), "r"(a3), "r"(b0), "r"(b1));
}

// ============================================================================
// Mask bit-pack: one warp per output uint64 (64 mask columns).
// ============================================================================
__global__ __launch_bounds__(256) void pack_mask_kernel(
    const int* __restrict__ mask, unsigned long long* __restrict__ packed)
{
    const int wid  = (blockIdx.x * blockDim.x + threadIdx.x) >> 5;
    const int lane = threadIdx.x & 31;
    const int row  = wid >> 6;
    const int word = wid & 63;
    const int* p = mask + (size_t)row * S_LEN + word * 64;
    unsigned lo = __ballot_sync(0xffffffffu, p[lane]      != 0);
    unsigned hi = __ballot_sync(0xffffffffu, p[lane + 32] != 0);
    if (lane == 0)
        packed[wid] = ((unsigned long long)hi << 32) | (unsigned long long)lo;
}

// ============================================================================
// tf32 GEMM, 3-stage cp.async pipeline, cvt.rna on fragment loads (RN operands):
// C[m0:+128, n0:+128] = A[M,K]*B[N,K]^T + bias. 8 warps (4M x 2N), 32x64/warp.
// ============================================================================
#define TGK 16
#define LA  20
#define ABUF (128 * LA)
#define GEMM_SMEM_BYTES (3 * 2 * ABUF * 4)

__device__ __forceinline__ void gemm_tf32_body(
    const float* __restrict__ A, const float* __restrict__ B,
    const float* __restrict__ bias, float* __restrict__ C,
    int K, int ldc, int m0, int n0, float* smbase)
{
    float* Asb = smbase;                 // 3 stages of A
    float* Bsb = smbase + 3 * ABUF;      // 3 stages of B

    const int tid  = threadIdx.x;
    const int w    = tid >> 5, lane = tid & 31;
    const int g    = lane >> 2, tig = lane & 3;
    const int wm   = w & 3, wn = w >> 2;
    const int r    = tid >> 2;                 // 0..63
    const int cg   = (tid & 3) * 4;            // 0,4,8,12

    const unsigned sA = (unsigned)__cvta_generic_to_shared(Asb);
    const unsigned sB = (unsigned)__cvta_generic_to_shared(Bsb);

    float c[2][8][4];
#pragma unroll
    for (int mt = 0; mt < 2; mt++)
#pragma unroll
        for (int nt = 0; nt < 8; nt++)
#pragma unroll
            for (int j = 0; j < 4; j++) c[mt][nt][j] = 0.f;

    const int nsteps = K / TGK;

    auto issue = [&](int step, int st) {
        const int k0 = step * TGK;
        const unsigned a_dst = sA + (unsigned)(st * ABUF + r * LA + cg) * 4u;
        const unsigned b_dst = sB + (unsigned)(st * ABUF + r * LA + cg) * 4u;
        cpa16(a_dst,                            A + (size_t)(m0 + r)      * K + k0 + cg);
        cpa16(a_dst + (unsigned)(64 * LA) * 4u, A + (size_t)(m0 + r + 64) * K + k0 + cg);
        cpa16(b_dst,                            B + (size_t)(n0 + r)      * K + k0 + cg);
        cpa16(b_dst + (unsigned)(64 * LA) * 4u, B + (size_t)(n0 + r + 64) * K + k0 + cg);
    };

    issue(0, 0); CP_COMMIT();
    issue(1, 1); CP_COMMIT();

    for (int i = 0; i < nsteps; i++) {
        CP_WAIT1();
        __syncthreads();
        if (i + 2 < nsteps) issue(i + 2, (i + 2) % 3);
        CP_COMMIT();

        const float* As = Asb + (i % 3) * ABUF;
        const float* Bs = Bsb + (i % 3) * ABUF;

#pragma unroll
        for (int kk = 0; kk < 2; kk++) {
            unsigned af[2][4];
#pragma unroll
            for (int mt = 0; mt < 2; mt++) {
                const int row = wm * 32 + mt * 16;
                af[mt][0] = f2tf32(As[(row + g)     * LA + kk * 8 + tig]);
                af[mt][1] = f2tf32(As[(row + g + 8) * LA + kk * 8 + tig]);
                af[mt][2] = f2tf32(As[(row + g)     * LA + kk * 8 + tig + 4]);
                af[mt][3] = f2tf32(As[(row + g + 8) * LA + kk * 8 + tig + 4]);
            }
#pragma unroll
            for (int nt = 0; nt < 8; nt++) {
                const int brow = wn * 64 + nt * 8 + g;
                unsigned bf0 = f2tf32(Bs[brow * LA + kk * 8 + tig]);
                unsigned bf1 = f2tf32(Bs[brow * LA + kk * 8 + tig + 4]);
                mma_tf32(c[0][nt], af[0][0], af[0][1], af[0][2], af[0][3], bf0, bf1);
                mma_tf32(c[1][nt], af[1][0], af[1][1], af[1][2], af[1][3], bf0, bf1);
            }
        }
    }

#pragma unroll
    for (int nt = 0; nt < 8; nt++) {
        const int col = n0 + wn * 64 + nt * 8 + 2 * tig;
        const float2 bv = *(const float2*)(bias + col);
#pragma unroll
        for (int mt = 0; mt < 2; mt++) {
            const int row = m0 + wm * 32 + mt * 16 + g;
            *(float2*)(C + (size_t)row * ldc + col) =
                make_float2(c[mt][nt][0] + bv.x, c[mt][nt][1] + bv.y);
            *(float2*)(C + (size_t)(row + 8) * ldc + col) =
                make_float2(c[mt][nt][2] + bv.x, c[mt][nt][3] + bv.y);
        }
    }
}

__global__ __launch_bounds__(256, 2) void qkv_gemm_kernel(
    const float* __restrict__ x,
    const float* __restrict__ wq, const float* __restrict__ bq,
    const float* __restrict__ wk, const float* __restrict__ bk,
    const float* __restrict__ wv, const float* __restrict__ bv,
    float* __restrict__ Qo, float* __restrict__ Ko, float* __restrict__ Vo)
{
    extern __shared__ float sm[];
    const int nb  = blockIdx.x;          // 0..11
    const int mat = nb >> 2;             // 0:Q 1:K 2:V
    const int n0  = (nb & 3) * 128;
    const int m0  = blockIdx.y * 128;
    const float* B    = (mat == 0) ? wq : (mat == 1) ? wk : wv;
    const float* bias = (mat == 0) ? bq : (mat == 1) ? bk : bv;
    float* C          = (mat == 0) ? Qo : (mat == 1) ? Ko : Vo;
    gemm_tf32_body(x, B, bias, C, IN_DIM, DMODEL, m0, n0, sm);
}

__global__ __launch_bounds__(256, 2) void dense_gemm_kernel(
    const float* __restrict__ A, const float* __restrict__ B,
    const float* __restrict__ bias, float* __restrict__ C)
{
    extern __shared__ float sm[];
    gemm_tf32_body(A, B, bias, C, DMODEL, DMODEL,
                   blockIdx.y * 128, blockIdx.x * 128, sm);
}

// ============================================================================
// Flash attention (R4 verbatim — measured 387 µs total): 512 threads, BQ=256,
// 1 CTA/SM, grid (16, 8) = 128 CTAs (one wave). tf32 mma; K/P fragments via
// ldmatrix.x4; Q frags hoisted to registers; cp.async double-buffered K/V;
// bit-packed mask; exp2-domain online softmax. P reuses Q smem (per-warp rows).
// ============================================================================
#define BQ   256
#define BKC  64
#define LQ   68
#define LK   68
#define LV   72
#define KBUF (BKC * LK)
#define VBUF (BKC * LV)

#define ATTN_SMEM_FLOATS (BQ * LQ + 2 * KBUF + 2 * VBUF)
#define ATTN_SMEM_BYTES  (ATTN_SMEM_FLOATS * 4)

#define SCALE2 0.1803368801f   // 0.125 * log2(e)

__global__ __launch_bounds__(512, 1) void attn_tc_kernel(
    const float* __restrict__ Q, const float* __restrict__ K,
    const float* __restrict__ V, const unsigned long long* __restrict__ mbits,
    float* __restrict__ O)
{
    extern __shared__ float sm[];
    float* QPs = sm;                       // [BQ][LQ] : Q, then P (per-warp rows)
    float* Ks  = sm + BQ * LQ;             // 2 x [BKC][LK]
    float* Vs  = Ks + 2 * KBUF;            // 2 x [BKC][LV]

    const unsigned sQP = (unsigned)__cvta_generic_to_shared(QPs);
    const unsigned sK  = (unsigned)__cvta_generic_to_shared(Ks);
    const unsigned sV  = (unsigned)__cvta_generic_to_shared(Vs);

    const int tid  = threadIdx.x;
    const int w    = tid >> 5;            // 0..15
    const int lane = tid & 31;
    const int g    = lane >> 2;           // 0..7
    const int tig  = lane & 3;            // 0..3
    const int lrow = lane & 7;            // ldmatrix row within matrix
    const int lm   = lane >> 3;           // ldmatrix matrix select 0..3
    const int h    = blockIdx.y;
    const int qb   = blockIdx.x;
    const int w16  = w * 16;

    const float* Qg = Q + ((size_t)h * S_LEN + (size_t)qb * BQ) * DKH;
    const float* Kg = K + (size_t)h * S_LEN * DKH;
    const float* Vg = V + (size_t)h * S_LEN * DKH;

    // copy slices: K/V chunk 64x64 floats, 1024 float4 / 512 thr = 2 each
    const int crow = tid >> 4;            // 0..31
    const int ccol = (tid & 15) * 4;      // 0,4,..,60

    auto issue_kv = [&](int kb, int bb) {
#pragma unroll
        for (int p = 0; p < 2; p++) {
            const int row = crow + p * 32;
            const size_t goff = (size_t)(kb * BKC + row) * DKH + ccol;
            cpa16(sK + (unsigned)(bb * KBUF + row * LK + ccol) * 4u, Kg + goff);
            cpa16(sV + (unsigned)(bb * VBUF + row * LV + ccol) * 4u, Vg + goff);
        }
    };

    // ---- prologue: Q tile (256x64) + K/V chunk 0, one cp.async group ----
#pragma unroll
    for (int p = 0; p < 8; p++) {
        const int f   = tid + p * 512;
        const int row = f >> 4;
        const int col = (f & 15) * 4;
        cpa16(sQP + (unsigned)(row * LQ + col) * 4u, Qg + (size_t)row * DKH + col);
    }
    issue_kv(0, 0);
    CP_COMMIT();
    CP_WAIT0();
    __syncthreads();

    // hoist Q fragments (RN tf32); frees this warp's QP rows for P reuse
    unsigned qa[8][4];
#pragma unroll
    for (int kk = 0; kk < 8; kk++) {
        qa[kk][0] = f2tf32(QPs[(w16 + g)     * LQ + kk * 8 + tig]);
        qa[kk][1] = f2tf32(QPs[(w16 + g + 8) * LQ + kk * 8 + tig]);
        qa[kk][2] = f2tf32(QPs[(w16 + g)     * LQ + kk * 8 + tig + 4]);
        qa[kk][3] = f2tf32(QPs[(w16 + g + 8) * LQ + kk * 8 + tig + 4]);
    }

    float m0 = -INFINITY, m1 = -INFINITY, l0 = 0.f, l1 = 0.f;
    float o[8][4];
#pragma unroll
    for (int nt = 0; nt < 8; nt++)
#pragma unroll
        for (int j = 0; j < 4; j++) o[nt][j] = 0.f;

    const int row0 = qb * BQ + w16 + g;
    const int row1 = row0 + 8;
    const unsigned long long* mb0p = mbits + (size_t)row0 * 64;
    const unsigned long long* mb1p = mbits + (size_t)row1 * 64;

    // lane-fixed ldmatrix address components
    const unsigned klane = (unsigned)(lrow * LK + lm * 4) * 4u;                    // K frags
    const unsigned plane = sQP +
        (unsigned)(((w16 + (lm & 1) * 8 + lrow) * LQ) + (lm >> 1) * 4) * 4u;       // P frags

    for (int kb = 0; kb < S_LEN / BKC; kb++) {
        CP_WAIT0();
        __syncthreads();

        const unsigned long long b0 = mb0p[kb] >> (2 * tig);
        const unsigned long long b1 = mb1p[kb] >> (2 * tig);

        if (kb + 1 < S_LEN / BKC) { issue_kv(kb + 1, (kb + 1) & 1); CP_COMMIT(); }

        const unsigned kbase = sK + (unsigned)((kb & 1) * KBUF) * 4u + klane;
        const float*   Vb    = Vs + (kb & 1) * VBUF;

        // ---- S = Q * K^T : K B-frags via ldmatrix.x4 (2 k-steps per LDSM) ----
        float s[8][4];
#pragma unroll
        for (int nt = 0; nt < 8; nt++) {
#pragma unroll
            for (int j = 0; j < 4; j++) s[nt][j] = 0.f;
            const unsigned bnt = kbase + (unsigned)(nt * 8 * LK) * 4u;
#pragma unroll
            for (int p = 0; p < 4; p++) {
                unsigned r0, r1, r2, r3;
                ldsm_x4(bnt + (unsigned)(p * 16) * 4u, r0, r1, r2, r3);
                mma_tf32(s[nt], qa[2*p][0], qa[2*p][1], qa[2*p][2], qa[2*p][3], r0, r1);
                mma_tf32(s[nt], qa[2*p+1][0], qa[2*p+1][1], qa[2*p+1][2], qa[2*p+1][3], r2, r3);
            }
        }

        // ---- mask + online softmax (exp2 domain) ----
        float mx0 = -INFINITY, mx1 = -INFINITY;
#pragma unroll
        for (int nt = 0; nt < 8; nt++) {
            s[nt][0] = fmaf(s[nt][0], SCALE2, ((b0 >> (nt * 8    )) & 1ull) ? -1e9f : 0.f);
            s[nt][1] = fmaf(s[nt][1], SCALE2, ((b0 >> (nt * 8 + 1)) & 1ull) ? -1e9f : 0.f);
            s[nt][2] = fmaf(s[nt][2], SCALE2, ((b1 >> (nt * 8    )) & 1ull) ? -1e9f : 0.f);
            s[nt][3] = fmaf(s[nt][3], SCALE2, ((b1 >> (nt * 8 + 1)) & 1ull) ? -1e9f : 0.f);
            mx0 = fmaxf(mx0, fmaxf(s[nt][0], s[nt][1]));
            mx1 = fmaxf(mx1, fmaxf(s[nt][2], s[nt][3]));
        }
        mx0 = fmaxf(mx0, __shfl_xor_sync(0xffffffffu, mx0, 1));
        mx0 = fmaxf(mx0, __shfl_xor_sync(0xffffffffu, mx0, 2));
        mx1 = fmaxf(mx1, __shfl_xor_sync(0xffffffffu, mx1, 1));
        mx1 = fmaxf(mx1, __shfl_xor_sync(0xffffffffu, mx1, 2));

        const float mn0 = fmaxf(m0, mx0), mn1 = fmaxf(m1, mx1);
        const float sc0 = ex2f(m0 - mn0), sc1 = ex2f(m1 - mn1);
        m0 = mn0; m1 = mn1;

        float rs0 = 0.f, rs1 = 0.f;
#pragma unroll
        for (int nt = 0; nt < 8; nt++) {
            const float p0 = ex2f(s[nt][0] - mn0);
            const float p1 = ex2f(s[nt][1] - mn0);
            const float p2 = ex2f(s[nt][2] - mn1);
            const float p3 = ex2f(s[nt][3] - mn1);
            rs0 += p0 + p1;
            rs1 += p2 + p3;
            *(float2*)&QPs[(w16 + g)     * LQ + nt * 8 + 2 * tig] =
                make_float2(f2tf32f(p0), f2tf32f(p1));
            *(float2*)&QPs[(w16 + g + 8) * LQ + nt * 8 + 2 * tig] =
                make_float2(f2tf32f(p2), f2tf32f(p3));
            o[nt][0] *= sc0; o[nt][1] *= sc0;
            o[nt][2] *= sc1; o[nt][3] *= sc1;
        }
        rs0 += __shfl_xor_sync(0xffffffffu, rs0, 1);
        rs0 += __shfl_xor_sync(0xffffffffu, rs0, 2);
        rs1 += __shfl_xor_sync(0xffffffffu, rs1, 1);
        rs1 += __shfl_xor_sync(0xffffffffu, rs1, 2);
        l0 = l0 * sc0 + rs0;
        l1 = l1 * sc1 + rs1;

        __syncwarp();   // P visible within warp (exclusive row ownership)

        // ---- O += P * V : P A-frags via ldmatrix.x4, V scalar (conflict-free) ----
#pragma unroll
        for (int kc = 0; kc < 8; kc++) {
            unsigned a0, a1, a2, a3;
            ldsm_x4(plane + (unsigned)(kc * 8) * 4u, a0, a1, a2, a3);
            const float* vr0 = Vb + (kc * 8 + tig)     * LV + g;
            const float* vr1 = Vb + (kc * 8 + tig + 4) * LV + g;
#pragma unroll
            for (int nt = 0; nt < 8; nt++) {
                unsigned bb0 = __float_as_uint(vr0[nt * 8]);
                unsigned bb1 = __float_as_uint(vr1[nt * 8]);
                mma_tf32(o[nt], a0, a1, a2, a3, bb0, bb1);
            }
        }
    }

    // ---- normalize + write AttnOut[token][h*64 + d] ----
    const float inv0 = 1.0f / l0, inv1 = 1.0f / l1;
    float* O0 = O + (size_t)row0 * DMODEL + h * DKH + 2 * tig;
    float* O1 = O + (size_t)row1 * DMODEL + h * DKH + 2 * tig;
#pragma unroll
    for (int nt = 0; nt < 8; nt++) {
        *(float2*)(O0 + nt * 8) = make_float2(o[nt][0] * inv0, o[nt][1] * inv0);
        *(float2*)(O1 + nt * 8) = make_float2(o[nt][2] * inv1, o[nt][3] * inv1);
    }
}

// ============================================================================
extern "C" void kernel_launch(void* const* d_in, const int* in_sizes, int n_in,
                              void* d_out, int out_size)
{
    const float* x       = (const float*)d_in[0];
    const int*   mask    = (const int*)  d_in[1];
    const float* wq_w    = (const float*)d_in[2];
    const float* wq_b    = (const float*)d_in[3];
    const float* wk_w    = (const float*)d_in[4];
    const float* wk_b    = (const float*)d_in[5];
    const float* wv_w    = (const float*)d_in[6];
    const float* wv_b    = (const float*)d_in[7];
    const float* dense_w = (const float*)d_in[8];
    const float* dense_b = (const float*)d_in[9];
    float* out = (float*)d_out;

    float *Qp, *Kp, *Vp, *AOp;
    unsigned long long* MBp;
    cudaGetSymbolAddress((void**)&Qp,  g_Q);
    cudaGetSymbolAddress((void**)&Kp,  g_K);
    cudaGetSymbolAddress((void**)&Vp,  g_V);
    cudaGetSymbolAddress((void**)&AOp, g_AO);
    cudaGetSymbolAddress((void**)&MBp, g_MB);

    cudaFuncSetAttribute(attn_tc_kernel,
                         cudaFuncAttributeMaxDynamicSharedMemorySize,
                         ATTN_SMEM_BYTES);
    cudaFuncSetAttribute(qkv_gemm_kernel,
                         cudaFuncAttributeMaxDynamicSharedMemorySize,
                         GEMM_SMEM_BYTES);
    cudaFuncSetAttribute(dense_gemm_kernel,
                         cudaFuncAttributeMaxDynamicSharedMemorySize,
                         GEMM_SMEM_BYTES);

    // 0) Bit-pack the mask (S*S int32 -> S x S/64 uint64, 2 MB, L2-resident)
    pack_mask_kernel<<<(S_LEN * 64 * 32) / 256, 256>>>(mask, MBp);

    // 1) Fused QKV projections (3-stage cp.async tf32 GEMM, RN operands)
    qkv_gemm_kernel<<<dim3(12, S_LEN / 128), 256, GEMM_SMEM_BYTES>>>(
        x, wq_w, wq_b, wk_w, wk_b, wv_w, wv_b, Qp, Kp, Vp);

    // 2) Masked flash attention (R4 kernel: 512 thr, ldmatrix, cp.async K/V)
    attn_tc_kernel<<<dim3(S_LEN / BQ, NHEAD), 512, ATTN_SMEM_BYTES>>>(
        Qp, Kp, Vp, MBp, AOp);

    // 3) Dense output projection (3-stage cp.async tf32 GEMM, RN operands)
    dense_gemm_kernel<<<dim3(DMODEL / 128, S_LEN / 128), 256, GEMM_SMEM_BYTES>>>(
        AOp, dense_w, dense_b, out);
}

// round 11
// speedup vs baseline: 1.9092x; 1.4607x over previous
#include <cuda_runtime.h>
#include <cuda_fp16.h>
#include <math.h>
#include <stddef.h>

// Problem constants (B=1)
#define S_LEN  4096
#define DMODEL 512
#define IN_DIM 512
#define NHEAD  8
#define DKH    64          // head dim

// ---------------- scratch (device globals; no allocations allowed) ----------
__device__ __half g_Qh[S_LEN * DMODEL];
__device__ __half g_Kh[S_LEN * DMODEL];
__device__ __half g_Vh[S_LEN * DMODEL];
__device__ float  g_AO[S_LEN * DMODEL];
__device__ unsigned long long g_MB[S_LEN * (S_LEN / 64)];   // bit-packed mask

// ---------------- helpers ----------------------------------------------------
__device__ __forceinline__ unsigned f2tf32(float x) {
    unsigned u;
    asm("cvt.rna.tf32.f32 %0, %1;" : "=r"(u) : "f"(x));
    return u;
}
__device__ __forceinline__ float ex2f(float x) {
    float y;
    asm("ex2.approx.ftz.f32 %0, %1;" : "=f"(y) : "f"(x));
    return y;
}
__device__ __forceinline__ void cpa16(unsigned dst_smem, const void* src) {
    asm volatile("cp.async.cg.shared.global [%0], [%1], 16;\n"
                 :: "r"(dst_smem), "l"(src));
}
#define CP_COMMIT() asm volatile("cp.async.commit_group;\n" ::: "memory")
#define CP_WAIT0()  asm volatile("cp.async.wait_group 0;\n" ::: "memory")
#define CP_WAIT1()  asm volatile("cp.async.wait_group 1;\n" ::: "memory")

__device__ __forceinline__ void ldsm_x4(unsigned addr,
    unsigned& r0, unsigned& r1, unsigned& r2, unsigned& r3)
{
    asm volatile("ldmatrix.sync.aligned.m8n8.x4.shared.b16 {%0,%1,%2,%3}, [%4];\n"
                 : "=r"(r0), "=r"(r1), "=r"(r2), "=r"(r3) : "r"(addr));
}
__device__ __forceinline__ void ldsm_x4_trans(unsigned addr,
    unsigned& r0, unsigned& r1, unsigned& r2, unsigned& r3)
{
    asm volatile("ldmatrix.sync.aligned.m8n8.x4.trans.shared.b16 {%0,%1,%2,%3}, [%4];\n"
                 : "=r"(r0), "=r"(r1), "=r"(r2), "=r"(r3) : "r"(addr));
}

__device__ __forceinline__ void mma_tf32(float c[4],
    unsigned a0, unsigned a1, unsigned a2, unsigned a3,
    unsigned b0, unsigned b1)
{
    asm volatile(
        "mma.sync.aligned.m16n8k8.row.col.f32.tf32.tf32.f32 "
        "{%0,%1,%2,%3}, {%4,%5,%6,%7}, {%8,%9}, {%0,%1,%2,%3};\n"
        : "+f"(c[0]), "+f"(c[1]), "+f"(c[2]), "+f"(c[3])
        : "r"(a0), "r"(a1), "r"(a2), "r"(a3), "r"(b0), "r"(b1));
}

__device__ __forceinline__ void mma_f16(float c[4],
    unsigned a0, unsigned a1, unsigned a2, unsigned a3,
    unsigned b0, unsigned b1)
{
    asm volatile(
        "mma.sync.aligned.m16n8k16.row.col.f32.f16.f16.f32 "
        "{%0,%1,%2,%3}, {%4,%5,%6,%7}, {%8,%9}, {%0,%1,%2,%3};\n"
        : "+f"(c[0]), "+f"(c[1]), "+f"(c[2]), "+f"(c[3])
        : "r"(a0), "r"(a1), "r"(a2), "r"(a3), "r"(b0), "r"(b1));
}

// ============================================================================
// Mask bit-pack: one warp per output uint64 (64 mask columns).
// ============================================================================
__global__ __launch_bounds__(256) void pack_mask_kernel(
    const int* __restrict__ mask, unsigned long long* __restrict__ packed)
{
    const int wid  = (blockIdx.x * blockDim.x + threadIdx.x) >> 5;
    const int lane = threadIdx.x & 31;
    const int row  = wid >> 6;
    const int word = wid & 63;
    const int* p = mask + (size_t)row * S_LEN + word * 64;
    unsigned lo = __ballot_sync(0xffffffffu, p[lane]      != 0);
    unsigned hi = __ballot_sync(0xffffffffu, p[lane + 32] != 0);
    if (lane == 0)
        packed[wid] = ((unsigned long long)hi << 32) | (unsigned long long)lo;
}

// ============================================================================
// tf32 GEMM, 3-stage cp.async pipeline, cvt.rna on fragment loads.
// C = A[M,K]*B[N,K]^T + bias, 128x128 tile. HALF_OUT: store __half output.
// ============================================================================
#define TGK 16
#define LA  20
#define ABUF (128 * LA)
#define GEMM_SMEM_BYTES (3 * 2 * ABUF * 4)

template<bool HALF_OUT>
__device__ __forceinline__ void gemm_tf32_body(
    const float* __restrict__ A, const float* __restrict__ B,
    const float* __restrict__ bias, void* __restrict__ C,
    int K, int ldc, int m0, int n0, float* smbase)
{
    float* Asb = smbase;
    float* Bsb = smbase + 3 * ABUF;

    const int tid  = threadIdx.x;
    const int w    = tid >> 5, lane = tid & 31;
    const int g    = lane >> 2, tig = lane & 3;
    const int wm   = w & 3, wn = w >> 2;
    const int r    = tid >> 2;
    const int cg   = (tid & 3) * 4;

    const unsigned sA = (unsigned)__cvta_generic_to_shared(Asb);
    const unsigned sB = (unsigned)__cvta_generic_to_shared(Bsb);

    float c[2][8][4];
#pragma unroll
    for (int mt = 0; mt < 2; mt++)
#pragma unroll
        for (int nt = 0; nt < 8; nt++)
#pragma unroll
            for (int j = 0; j < 4; j++) c[mt][nt][j] = 0.f;

    const int nsteps = K / TGK;

    auto issue = [&](int step, int st) {
        const int k0 = step * TGK;
        const unsigned a_dst = sA + (unsigned)(st * ABUF + r * LA + cg) * 4u;
        const unsigned b_dst = sB + (unsigned)(st * ABUF + r * LA + cg) * 4u;
        cpa16(a_dst,                            A + (size_t)(m0 + r)      * K + k0 + cg);
        cpa16(a_dst + (unsigned)(64 * LA) * 4u, A + (size_t)(m0 + r + 64) * K + k0 + cg);
        cpa16(b_dst,                            B + (size_t)(n0 + r)      * K + k0 + cg);
        cpa16(b_dst + (unsigned)(64 * LA) * 4u, B + (size_t)(n0 + r + 64) * K + k0 + cg);
    };

    issue(0, 0); CP_COMMIT();
    issue(1, 1); CP_COMMIT();

    for (int i = 0; i < nsteps; i++) {
        CP_WAIT1();
        __syncthreads();
        if (i + 2 < nsteps) issue(i + 2, (i + 2) % 3);
        CP_COMMIT();

        const float* As = Asb + (i % 3) * ABUF;
        const float* Bs = Bsb + (i % 3) * ABUF;

#pragma unroll
        for (int kk = 0; kk < 2; kk++) {
            unsigned af[2][4];
#pragma unroll
            for (int mt = 0; mt < 2; mt++) {
                const int row = wm * 32 + mt * 16;
                af[mt][0] = f2tf32(As[(row + g)     * LA + kk * 8 + tig]);
                af[mt][1] = f2tf32(As[(row + g + 8) * LA + kk * 8 + tig]);
                af[mt][2] = f2tf32(As[(row + g)     * LA + kk * 8 + tig + 4]);
                af[mt][3] = f2tf32(As[(row + g + 8) * LA + kk * 8 + tig + 4]);
            }
#pragma unroll
            for (int nt = 0; nt < 8; nt++) {
                const int brow = wn * 64 + nt * 8 + g;
                unsigned bf0 = f2tf32(Bs[brow * LA + kk * 8 + tig]);
                unsigned bf1 = f2tf32(Bs[brow * LA + kk * 8 + tig + 4]);
                mma_tf32(c[0][nt], af[0][0], af[0][1], af[0][2], af[0][3], bf0, bf1);
                mma_tf32(c[1][nt], af[1][0], af[1][1], af[1][2], af[1][3], bf0, bf1);
            }
        }
    }

#pragma unroll
    for (int nt = 0; nt < 8; nt++) {
        const int col = n0 + wn * 64 + nt * 8 + 2 * tig;
        const float2 bv = *(const float2*)(bias + col);
#pragma unroll
        for (int mt = 0; mt < 2; mt++) {
            const int row = m0 + wm * 32 + mt * 16 + g;
            if (HALF_OUT) {
                __half* Ch = (__half*)C;
                *(__half2*)(Ch + (size_t)row * ldc + col) =
                    __floats2half2_rn(c[mt][nt][0] + bv.x, c[mt][nt][1] + bv.y);
                *(__half2*)(Ch + (size_t)(row + 8) * ldc + col) =
                    __floats2half2_rn(c[mt][nt][2] + bv.x, c[mt][nt][3] + bv.y);
            } else {
                float* Cf = (float*)C;
                *(float2*)(Cf + (size_t)row * ldc + col) =
                    make_float2(c[mt][nt][0] + bv.x, c[mt][nt][1] + bv.y);
                *(float2*)(Cf + (size_t)(row + 8) * ldc + col) =
                    make_float2(c[mt][nt][2] + bv.x, c[mt][nt][3] + bv.y);
            }
        }
    }
}

__global__ __launch_bounds__(256, 2) void qkv_gemm_kernel(
    const float* __restrict__ x,
    const float* __restrict__ wq, const float* __restrict__ bq,
    const float* __restrict__ wk, const float* __restrict__ bk,
    const float* __restrict__ wv, const float* __restrict__ bv,
    __half* __restrict__ Qo, __half* __restrict__ Ko, __half* __restrict__ Vo)
{
    extern __shared__ float sm[];
    const int nb  = blockIdx.x;          // 0..11
    const int mat = nb >> 2;             // 0:Q 1:K 2:V
    const int n0  = (nb & 3) * 128;
    const int m0  = blockIdx.y * 128;
    const float* B    = (mat == 0) ? wq : (mat == 1) ? wk : wv;
    const float* bias = (mat == 0) ? bq : (mat == 1) ? bk : bv;
    __half* C         = (mat == 0) ? Qo : (mat == 1) ? Ko : Vo;
    gemm_tf32_body<true>(x, B, bias, C, IN_DIM, DMODEL, m0, n0, sm);
}

__global__ __launch_bounds__(256, 2) void dense_gemm_kernel(
    const float* __restrict__ A, const float* __restrict__ B,
    const float* __restrict__ bias, float* __restrict__ C)
{
    extern __shared__ float sm[];
    gemm_tf32_body<false>(A, B, bias, C, DMODEL, DMODEL,
                          blockIdx.y * 128, blockIdx.x * 128, sm);
}

// ============================================================================
// Flash attention v9 (fp16 operands, m16n8k16 mma, fp32 softmax/accum):
// 512 threads, BQ=256, 1 CTA/SM, grid (16, 8). Q A-frags hoisted (16 regs);
// K B-frags ldmatrix.x4; P stored __half2, reloaded as A-frags ldmatrix.x4;
// V B-frags via ldmatrix.x4.TRANS on natural [token][dim] layout.
// Row stride 72 halves (144 B) -> conflict-free LDSM phases and P stores.
// ============================================================================
#define BQ    256
#define BKC   64
#define LH    72                      // halves per row (Q/P, K, V)
#define QPBUF (BQ * LH)               // halves
#define KVBUF (BKC * LH)              // halves (one K or V stage)

#define ATTN_SMEM_BYTES ((QPBUF + 4 * KVBUF) * 2)

#define SCALE2 0.1803368801f          // 0.125 * log2(e)

__global__ __launch_bounds__(512, 1) void attn_tc_kernel(
    const __half* __restrict__ Q, const __half* __restrict__ K,
    const __half* __restrict__ V, const unsigned long long* __restrict__ mbits,
    float* __restrict__ O)
{
    extern __shared__ __half smh[];
    __half* QPs = smh;                     // [BQ][LH] : Q, then P (per-warp rows)
    __half* Ks  = smh + QPBUF;             // 2 x [BKC][LH]
    __half* Vs  = Ks + 2 * KVBUF;          // 2 x [BKC][LH]

    const unsigned sQP = (unsigned)__cvta_generic_to_shared(QPs);
    const unsigned sK  = (unsigned)__cvta_generic_to_shared(Ks);
    const unsigned sV  = (unsigned)__cvta_generic_to_shared(Vs);

    const int tid  = threadIdx.x;
    const int w    = tid >> 5;            // 0..15
    const int lane = tid & 31;
    const int g    = lane >> 2;           // 0..7
    const int tig  = lane & 3;            // 0..3
    const int h    = blockIdx.y;
    const int qb   = blockIdx.x;
    const int w16  = w * 16;

    const __half* Qg = Q + ((size_t)h * S_LEN + (size_t)qb * BQ) * DKH;
    const __half* Kg = K + (size_t)h * S_LEN * DKH;
    const __half* Vg = V + (size_t)h * S_LEN * DKH;

    // K/V chunk copy: 64 rows x 128B each; 512 segs per tile; 1 K + 1 V per thr
    const int crow = tid >> 3;            // 0..63
    const int cseg = (tid & 7) * 8;       // halves offset 0..56

    auto issue_kv = [&](int kb, int bb) {
        const size_t goff = (size_t)(kb * BKC + crow) * DKH + cseg;
        cpa16(sK + (unsigned)(bb * KVBUF + crow * LH + cseg) * 2u, Kg + goff);
        cpa16(sV + (unsigned)(bb * KVBUF + crow * LH + cseg) * 2u, Vg + goff);
    };

    // ---- prologue: Q tile (256x64 halves) + K/V chunk 0 ----
#pragma unroll
    for (int p = 0; p < 4; p++) {
        const int f   = tid + p * 512;    // 0..2047
        const int row = f >> 3;
        const int seg = (f & 7) * 8;
        cpa16(sQP + (unsigned)(row * LH + seg) * 2u, Qg + (size_t)row * DKH + seg);
    }
    issue_kv(0, 0);
    CP_COMMIT();
    CP_WAIT0();
    __syncthreads();

    // lane-fixed ldmatrix offsets (bytes)
    // A-frag pattern (Q and P): row = base + ((lane>>3)&1)*8 + (lane&7); coloff = (lane>>4)*8
    const int afrow = ((lane >> 3) & 1) * 8 + (lane & 7);
    const int afcol = (lane >> 4) * 8;
    // K B-frag pattern: token = (lane&7); dim = (lane>>3)*8
    const unsigned klane = (unsigned)((lane & 7) * LH + (lane >> 3) * 8) * 2u;
    // V B-frag (trans): token = ((lane>>3)&1)*8 + (lane&7); dim = (lane>>4)*8
    const unsigned vlane = (unsigned)((((lane >> 3) & 1) * 8 + (lane & 7)) * LH
                                      + (lane >> 4) * 8) * 2u;
    const unsigned qbase = sQP + (unsigned)((w16 + afrow) * LH + afcol) * 2u;

    // hoist Q fragments: 4 k16-steps x 4 regs
    unsigned qa[4][4];
#pragma unroll
    for (int ks = 0; ks < 4; ks++)
        ldsm_x4(qbase + (unsigned)(ks * 16) * 2u,
                qa[ks][0], qa[ks][1], qa[ks][2], qa[ks][3]);

    float m0 = -INFINITY, m1 = -INFINITY, l0 = 0.f, l1 = 0.f;
    float o[8][4];
#pragma unroll
    for (int nt = 0; nt < 8; nt++)
#pragma unroll
        for (int j = 0; j < 4; j++) o[nt][j] = 0.f;

    const int row0 = qb * BQ + w16 + g;
    const int row1 = row0 + 8;
    const unsigned long long* mb0p = mbits + (size_t)row0 * 64;
    const unsigned long long* mb1p = mbits + (size_t)row1 * 64;

    for (int kb = 0; kb < S_LEN / BKC; kb++) {
        CP_WAIT0();
        __syncthreads();

        const unsigned long long b0 = mb0p[kb] >> (2 * tig);
        const unsigned long long b1 = mb1p[kb] >> (2 * tig);

        if (kb + 1 < S_LEN / BKC) { issue_kv(kb + 1, (kb + 1) & 1); CP_COMMIT(); }

        const unsigned kbase = sK + (unsigned)((kb & 1) * KVBUF) * 2u + klane;
        const unsigned vbase = sV + (unsigned)((kb & 1) * KVBUF) * 2u + vlane;

        // ---- S = Q * K^T : per nt, 2 LDSM (each covers 2 k16-steps), 4 mma ----
        float s[8][4];
#pragma unroll
        for (int nt = 0; nt < 8; nt++) {
#pragma unroll
            for (int j = 0; j < 4; j++) s[nt][j] = 0.f;
            const unsigned bnt = kbase + (unsigned)(nt * 8 * LH) * 2u;
            unsigned r0, r1, r2, r3;
            ldsm_x4(bnt, r0, r1, r2, r3);                        // dims 0-31
            mma_f16(s[nt], qa[0][0], qa[0][1], qa[0][2], qa[0][3], r0, r1);
            mma_f16(s[nt], qa[1][0], qa[1][1], qa[1][2], qa[1][3], r2, r3);
            ldsm_x4(bnt + 64u, r0, r1, r2, r3);                  // dims 32-63
            mma_f16(s[nt], qa[2][0], qa[2][1], qa[2][2], qa[2][3], r0, r1);
            mma_f16(s[nt], qa[3][0], qa[3][1], qa[3][2], qa[3][3], r2, r3);
        }

        // ---- mask + online softmax (exp2 domain) ----
        float mx0 = -INFINITY, mx1 = -INFINITY;
#pragma unroll
        for (int nt = 0; nt < 8; nt++) {
            s[nt][0] = fmaf(s[nt][0], SCALE2, ((b0 >> (nt * 8    )) & 1ull) ? -1e9f : 0.f);
            s[nt][1] = fmaf(s[nt][1], SCALE2, ((b0 >> (nt * 8 + 1)) & 1ull) ? -1e9f : 0.f);
            s[nt][2] = fmaf(s[nt][2], SCALE2, ((b1 >> (nt * 8    )) & 1ull) ? -1e9f : 0.f);
            s[nt][3] = fmaf(s[nt][3], SCALE2, ((b1 >> (nt * 8 + 1)) & 1ull) ? -1e9f : 0.f);
            mx0 = fmaxf(mx0, fmaxf(s[nt][0], s[nt][1]));
            mx1 = fmaxf(mx1, fmaxf(s[nt][2], s[nt][3]));
        }
        mx0 = fmaxf(mx0, __shfl_xor_sync(0xffffffffu, mx0, 1));
        mx0 = fmaxf(mx0, __shfl_xor_sync(0xffffffffu, mx0, 2));
        mx1 = fmaxf(mx1, __shfl_xor_sync(0xffffffffu, mx1, 1));
        mx1 = fmaxf(mx1, __shfl_xor_sync(0xffffffffu, mx1, 2));

        const float mn0 = fmaxf(m0, mx0), mn1 = fmaxf(m1, mx1);
        const float sc0 = ex2f(m0 - mn0), sc1 = ex2f(m1 - mn1);
        m0 = mn0; m1 = mn1;

        float rs0 = 0.f, rs1 = 0.f;
#pragma unroll
        for (int nt = 0; nt < 8; nt++) {
            const float p0 = ex2f(s[nt][0] - mn0);
            const float p1 = ex2f(s[nt][1] - mn0);
            const float p2 = ex2f(s[nt][2] - mn1);
            const float p3 = ex2f(s[nt][3] - mn1);
            rs0 += p0 + p1;
            rs1 += p2 + p3;
            *(__half2*)&QPs[(w16 + g)     * LH + nt * 8 + 2 * tig] = __floats2half2_rn(p0, p1);
            *(__half2*)&QPs[(w16 + g + 8) * LH + nt * 8 + 2 * tig] = __floats2half2_rn(p2, p3);
            o[nt][0] *= sc0; o[nt][1] *= sc0;
            o[nt][2] *= sc1; o[nt][3] *= sc1;
        }
        rs0 += __shfl_xor_sync(0xffffffffu, rs0, 1);
        rs0 += __shfl_xor_sync(0xffffffffu, rs0, 2);
        rs1 += __shfl_xor_sync(0xffffffffu, rs1, 1);
        rs1 += __shfl_xor_sync(0xffffffffu, rs1, 2);
        l0 = l0 * sc0 + rs0;
        l1 = l1 * sc1 + rs1;

        __syncwarp();   // P visible within warp (exclusive row ownership)

        // ---- O += P * V : P A-frags (ldmatrix), V B-frags (ldmatrix.trans) ----
        const unsigned pbase = sQP + (unsigned)((w16 + afrow) * LH + afcol) * 2u;
#pragma unroll
        for (int kc = 0; kc < 4; kc++) {
            unsigned pa0, pa1, pa2, pa3;
            ldsm_x4(pbase + (unsigned)(kc * 16) * 2u, pa0, pa1, pa2, pa3);
            const unsigned vkc = vbase + (unsigned)(kc * 16 * LH) * 2u;
#pragma unroll
            for (int ntp = 0; ntp < 4; ntp++) {
                unsigned r0, r1, r2, r3;
                ldsm_x4_trans(vkc + (unsigned)(ntp * 16) * 2u, r0, r1, r2, r3);
                mma_f16(o[2 * ntp],     pa0, pa1, pa2, pa3, r0, r1);
                mma_f16(o[2 * ntp + 1], pa0, pa1, pa2, pa3, r2, r3);
            }
        }
    }

    // ---- normalize + write AttnOut[token][h*64 + d] (fp32) ----
    const float inv0 = 1.0f / l0, inv1 = 1.0f / l1;
    float* O0 = O + (size_t)row0 * DMODEL + h * DKH + 2 * tig;
    float* O1 = O + (size_t)row1 * DMODEL + h * DKH + 2 * tig;
#pragma unroll
    for (int nt = 0; nt < 8; nt++) {
        *(float2*)(O0 + nt * 8) = make_float2(o[nt][0] * inv0, o[nt][1] * inv0);
        *(float2*)(O1 + nt * 8) = make_float2(o[nt][2] * inv1, o[nt][3] * inv1);
    }
}

// ============================================================================
extern "C" void kernel_launch(void* const* d_in, const int* in_sizes, int n_in,
                              void* d_out, int out_size)
{
    const float* x       = (const float*)d_in[0];
    const int*   mask    = (const int*)  d_in[1];
    const float* wq_w    = (const float*)d_in[2];
    const float* wq_b    = (const float*)d_in[3];
    const float* wk_w    = (const float*)d_in[4];
    const float* wk_b    = (const float*)d_in[5];
    const float* wv_w    = (const float*)d_in[6];
    const float* wv_b    = (const float*)d_in[7];
    const float* dense_w = (const float*)d_in[8];
    const float* dense_b = (const float*)d_in[9];
    float* out = (float*)d_out;

    __half *Qp, *Kp, *Vp;
    float *AOp;
    unsigned long long* MBp;
    cudaGetSymbolAddress((void**)&Qp,  g_Qh);
    cudaGetSymbolAddress((void**)&Kp,  g_Kh);
    cudaGetSymbolAddress((void**)&Vp,  g_Vh);
    cudaGetSymbolAddress((void**)&AOp, g_AO);
    cudaGetSymbolAddress((void**)&MBp, g_MB);

    cudaFuncSetAttribute(attn_tc_kernel,
                         cudaFuncAttributeMaxDynamicSharedMemorySize,
                         ATTN_SMEM_BYTES);
    cudaFuncSetAttribute(qkv_gemm_kernel,
                         cudaFuncAttributeMaxDynamicSharedMemorySize,
                         GEMM_SMEM_BYTES);
    cudaFuncSetAttribute(dense_gemm_kernel,
                         cudaFuncAttributeMaxDynamicSharedMemorySize,
                         GEMM_SMEM_BYTES);

    // 0) Bit-pack the mask (S*S int32 -> S x S/64 uint64, 2 MB, L2-resident)
    pack_mask_kernel<<<(S_LEN * 64 * 32) / 256, 256>>>(mask, MBp);

    // 1) Fused QKV projections (tf32 GEMM, fp16 outputs)
    qkv_gemm_kernel<<<dim3(12, S_LEN / 128), 256, GEMM_SMEM_BYTES>>>(
        x, wq_w, wq_b, wk_w, wk_b, wv_w, wv_b, Qp, Kp, Vp);

    // 2) Masked flash attention (fp16 m16n8k16 mma)
    attn_tc_kernel<<<dim3(S_LEN / BQ, NHEAD), 512, ATTN_SMEM_BYTES>>>(
        Qp, Kp, Vp, MBp, AOp);

    // 3) Dense output projection (tf32 GEMM, fp32)
    dense_gemm_kernel<<<dim3(DMODEL / 128, S_LEN / 128), 256, GEMM_SMEM_BYTES>>>(
        AOp, dense_w, dense_b, out);
}

// round 12
// speedup vs baseline: 2.1735x; 1.1384x over previous
#include <cuda_runtime.h>
#include <cuda_fp16.h>
#include <math.h>
#include <stddef.h>

// Problem constants (B=1)
#define S_LEN  4096
#define DMODEL 512
#define IN_DIM 512
#define NHEAD  8
#define DKH    64          // head dim

// ---------------- scratch (device globals; no allocations allowed) ----------
__device__ __half g_xh[S_LEN * IN_DIM];     // x in fp16
__device__ __half g_Wq[DMODEL * IN_DIM];    // weights in fp16
__device__ __half g_Wk[DMODEL * IN_DIM];
__device__ __half g_Wv[DMODEL * IN_DIM];
__device__ __half g_Wd[DMODEL * DMODEL];
__device__ __half g_Qh[S_LEN * DMODEL];
__device__ __half g_Kh[S_LEN * DMODEL];
__device__ __half g_Vh[S_LEN * DMODEL];
__device__ __half g_AOh[S_LEN * DMODEL];    // attention output fp16
__device__ unsigned long long g_MB[S_LEN * (S_LEN / 64)];   // bit-packed mask

// ---------------- helpers ----------------------------------------------------
__device__ __forceinline__ float ex2f(float x) {
    float y;
    asm("ex2.approx.ftz.f32 %0, %1;" : "=f"(y) : "f"(x));
    return y;
}
__device__ __forceinline__ void cpa16(unsigned dst_smem, const void* src) {
    asm volatile("cp.async.cg.shared.global [%0], [%1], 16;\n"
                 :: "r"(dst_smem), "l"(src));
}
#define CP_COMMIT() asm volatile("cp.async.commit_group;\n" ::: "memory")
#define CP_WAIT0()  asm volatile("cp.async.wait_group 0;\n" ::: "memory")
#define CP_WAIT1()  asm volatile("cp.async.wait_group 1;\n" ::: "memory")

__device__ __forceinline__ void ldsm_x4(unsigned addr,
    unsigned& r0, unsigned& r1, unsigned& r2, unsigned& r3)
{
    asm volatile("ldmatrix.sync.aligned.m8n8.x4.shared.b16 {%0,%1,%2,%3}, [%4];\n"
                 : "=r"(r0), "=r"(r1), "=r"(r2), "=r"(r3) : "r"(addr));
}
__device__ __forceinline__ void ldsm_x4_trans(unsigned addr,
    unsigned& r0, unsigned& r1, unsigned& r2, unsigned& r3)
{
    asm volatile("ldmatrix.sync.aligned.m8n8.x4.trans.shared.b16 {%0,%1,%2,%3}, [%4];\n"
                 : "=r"(r0), "=r"(r1), "=r"(r2), "=r"(r3) : "r"(addr));
}

__device__ __forceinline__ void mma_f16(float c[4],
    unsigned a0, unsigned a1, unsigned a2, unsigned a3,
    unsigned b0, unsigned b1)
{
    asm volatile(
        "mma.sync.aligned.m16n8k16.row.col.f32.f16.f16.f32 "
        "{%0,%1,%2,%3}, {%4,%5,%6,%7}, {%8,%9}, {%0,%1,%2,%3};\n"
        : "+f"(c[0]), "+f"(c[1]), "+f"(c[2]), "+f"(c[3])
        : "r"(a0), "r"(a1), "r"(a2), "r"(a3), "r"(b0), "r"(b1));
}

// ============================================================================
// fp32 -> fp16 convert (float4 granular)
// ============================================================================
__global__ __launch_bounds__(256) void f2h_kernel(
    const float* __restrict__ s, __half* __restrict__ d, int n4)
{
    const int i = blockIdx.x * blockDim.x + threadIdx.x;
    if (i < n4) {
        const float4 v = ((const float4*)s)[i];
        __half2* dp = (__half2*)d + i * 2;
        dp[0] = __floats2half2_rn(v.x, v.y);
        dp[1] = __floats2half2_rn(v.z, v.w);
    }
}

// ============================================================================
// Mask bit-pack: one warp per output uint64 (64 mask columns).
// ============================================================================
__global__ __launch_bounds__(256) void pack_mask_kernel(
    const int* __restrict__ mask, unsigned long long* __restrict__ packed)
{
    const int wid  = (blockIdx.x * blockDim.x + threadIdx.x) >> 5;
    const int lane = threadIdx.x & 31;
    const int row  = wid >> 6;
    const int word = wid & 63;
    const int* p = mask + (size_t)row * S_LEN + word * 64;
    unsigned lo = __ballot_sync(0xffffffffu, p[lane]      != 0);
    unsigned hi = __ballot_sync(0xffffffffu, p[lane + 32] != 0);
    if (lane == 0)
        packed[wid] = ((unsigned long long)hi << 32) | (unsigned long long)lo;
}

// ============================================================================
// fp16 GEMM (m16n8k16), 3-stage cp.async pipeline, ldmatrix fragments:
// C[m0:+128, n0:+128] = A[M,K]*B[N,K]^T + bias. 8 warps (4M x 2N), 32x64/warp.
// Fragment lane patterns identical to the verified attention kernel.
// ============================================================================
#define HGK  32                       // k-step (halves)
#define LGH  40                       // smem row stride (halves)
#define HBUF (128 * LGH)              // one stage of one operand (halves)
#define GEMM_SMEM_BYTES (3 * 2 * HBUF * 2)

template<bool HALF_OUT>
__device__ __forceinline__ void gemm_f16_body(
    const __half* __restrict__ A, const __half* __restrict__ B,
    const float* __restrict__ bias, void* __restrict__ C,
    int K, int ldc, int m0, int n0, __half* smbase)
{
    __half* Asb = smbase;             // 3 stages of A
    __half* Bsb = smbase + 3 * HBUF;  // 3 stages of B

    const int tid  = threadIdx.x;
    const int w    = tid >> 5, lane = tid & 31;
    const int g    = lane >> 2, tig = lane & 3;
    const int wm   = w & 3, wn = w >> 2;

    const unsigned sA = (unsigned)__cvta_generic_to_shared(Asb);
    const unsigned sB = (unsigned)__cvta_generic_to_shared(Bsb);

    // lane-fixed ldmatrix offsets (verified patterns from attention kernel)
    const int afrow = ((lane >> 3) & 1) * 8 + (lane & 7);
    const int afcol = (lane >> 4) * 8;
    const unsigned alane = (unsigned)((wm * 32 + afrow) * LGH + afcol) * 2u;
    const unsigned blane = (unsigned)((wn * 64 + (lane & 7)) * LGH + (lane >> 3) * 8) * 2u;

    float c[2][8][4];
#pragma unroll
    for (int mt = 0; mt < 2; mt++)
#pragma unroll
        for (int nt = 0; nt < 8; nt++)
#pragma unroll
            for (int j = 0; j < 4; j++) c[mt][nt][j] = 0.f;

    const int nsteps = K / HGK;

    // copy: A/B tiles 128 rows x 32 halves (64 B); 512 segs each; 2+2 per thread
    const int r  = tid >> 1;              // 0..127
    const int ch = (tid & 1) * 16;        // halves: 0 or 16

    auto issue = [&](int step, int st) {
        const int k0 = step * HGK;
        const unsigned a_dst = sA + (unsigned)(st * HBUF + r * LGH + ch) * 2u;
        const unsigned b_dst = sB + (unsigned)(st * HBUF + r * LGH + ch) * 2u;
        cpa16(a_dst,       A + (size_t)(m0 + r) * K + k0 + ch);
        cpa16(a_dst + 16u, A + (size_t)(m0 + r) * K + k0 + ch + 8);
        cpa16(b_dst,       B + (size_t)(n0 + r) * K + k0 + ch);
        cpa16(b_dst + 16u, B + (size_t)(n0 + r) * K + k0 + ch + 8);
    };

    issue(0, 0); CP_COMMIT();
    issue(1, 1); CP_COMMIT();

    for (int i = 0; i < nsteps; i++) {
        CP_WAIT1();
        __syncthreads();
        if (i + 2 < nsteps) issue(i + 2, (i + 2) % 3);
        CP_COMMIT();

        const unsigned abase = sA + (unsigned)((i % 3) * HBUF) * 2u + alane;
        const unsigned bbase = sB + (unsigned)((i % 3) * HBUF) * 2u + blane;

        // A fragments: 2 m16-tiles x 2 k16-steps
        unsigned a[2][2][4];
#pragma unroll
        for (int mt = 0; mt < 2; mt++) {
            const unsigned am = abase + (unsigned)(mt * 16 * LGH) * 2u;
            ldsm_x4(am,       a[mt][0][0], a[mt][0][1], a[mt][0][2], a[mt][0][3]);
            ldsm_x4(am + 32u, a[mt][1][0], a[mt][1][1], a[mt][1][2], a[mt][1][3]);
        }

#pragma unroll
        for (int nt = 0; nt < 8; nt++) {
            unsigned r0, r1, r2, r3;        // one LDSM covers n8 x k32
            ldsm_x4(bbase + (unsigned)(nt * 8 * LGH) * 2u, r0, r1, r2, r3);
            mma_f16(c[0][nt], a[0][0][0], a[0][0][1], a[0][0][2], a[0][0][3], r0, r1);
            mma_f16(c[0][nt], a[0][1][0], a[0][1][1], a[0][1][2], a[0][1][3], r2, r3);
            mma_f16(c[1][nt], a[1][0][0], a[1][0][1], a[1][0][2], a[1][0][3], r0, r1);
            mma_f16(c[1][nt], a[1][1][0], a[1][1][1], a[1][1][2], a[1][1][3], r2, r3);
        }
    }

#pragma unroll
    for (int nt = 0; nt < 8; nt++) {
        const int col = n0 + wn * 64 + nt * 8 + 2 * tig;
        const float2 bv = *(const float2*)(bias + col);
#pragma unroll
        for (int mt = 0; mt < 2; mt++) {
            const int row = m0 + wm * 32 + mt * 16 + g;
            if (HALF_OUT) {
                __half* Ch = (__half*)C;
                *(__half2*)(Ch + (size_t)row * ldc + col) =
                    __floats2half2_rn(c[mt][nt][0] + bv.x, c[mt][nt][1] + bv.y);
                *(__half2*)(Ch + (size_t)(row + 8) * ldc + col) =
                    __floats2half2_rn(c[mt][nt][2] + bv.x, c[mt][nt][3] + bv.y);
            } else {
                float* Cf = (float*)C;
                *(float2*)(Cf + (size_t)row * ldc + col) =
                    make_float2(c[mt][nt][0] + bv.x, c[mt][nt][1] + bv.y);
                *(float2*)(Cf + (size_t)(row + 8) * ldc + col) =
                    make_float2(c[mt][nt][2] + bv.x, c[mt][nt][3] + bv.y);
            }
        }
    }
}

__global__ __launch_bounds__(256, 2) void qkv_gemm_kernel(
    const __half* __restrict__ x,
    const __half* __restrict__ wq, const float* __restrict__ bq,
    const __half* __restrict__ wk, const float* __restrict__ bk,
    const __half* __restrict__ wv, const float* __restrict__ bv,
    __half* __restrict__ Qo, __half* __restrict__ Ko, __half* __restrict__ Vo)
{
    extern __shared__ __half smh[];
    const int nb  = blockIdx.x;          // 0..11
    const int mat = nb >> 2;             // 0:Q 1:K 2:V
    const int n0  = (nb & 3) * 128;
    const int m0  = blockIdx.y * 128;
    const __half* B   = (mat == 0) ? wq : (mat == 1) ? wk : wv;
    const float* bias = (mat == 0) ? bq : (mat == 1) ? bk : bv;
    __half* C         = (mat == 0) ? Qo : (mat == 1) ? Ko : Vo;
    gemm_f16_body<true>(x, B, bias, C, IN_DIM, DMODEL, m0, n0, smh);
}

__global__ __launch_bounds__(256, 2) void dense_gemm_kernel(
    const __half* __restrict__ A, const __half* __restrict__ B,
    const float* __restrict__ bias, float* __restrict__ C)
{
    extern __shared__ __half smh[];
    gemm_f16_body<false>(A, B, bias, C, DMODEL, DMODEL,
                         blockIdx.y * 128, blockIdx.x * 128, smh);
}

// ============================================================================
// Flash attention (R10 proven, fp16 m16n8k16): 512 threads, BQ=256, 1 CTA/SM,
// grid (16, 8). Q A-frags hoisted; K B-frags ldmatrix.x4; P as __half2 reloaded
// via ldmatrix.x4; V B-frags via ldmatrix.x4.trans. Output now fp16.
// ============================================================================
#define BQ    256
#define BKC   64
#define LH    72                      // halves per row (Q/P, K, V)
#define QPBUF (BQ * LH)
#define KVBUF (BKC * LH)

#define ATTN_SMEM_BYTES ((QPBUF + 4 * KVBUF) * 2)

#define SCALE2 0.1803368801f          // 0.125 * log2(e)

__global__ __launch_bounds__(512, 1) void attn_tc_kernel(
    const __half* __restrict__ Q, const __half* __restrict__ K,
    const __half* __restrict__ V, const unsigned long long* __restrict__ mbits,
    __half* __restrict__ O)
{
    extern __shared__ __half smh[];
    __half* QPs = smh;                     // [BQ][LH] : Q, then P (per-warp rows)
    __half* Ks  = smh + QPBUF;             // 2 x [BKC][LH]
    __half* Vs  = Ks + 2 * KVBUF;          // 2 x [BKC][LH]

    const unsigned sQP = (unsigned)__cvta_generic_to_shared(QPs);
    const unsigned sK  = (unsigned)__cvta_generic_to_shared(Ks);
    const unsigned sV  = (unsigned)__cvta_generic_to_shared(Vs);

    const int tid  = threadIdx.x;
    const int w    = tid >> 5;            // 0..15
    const int lane = tid & 31;
    const int g    = lane >> 2;           // 0..7
    const int tig  = lane & 3;            // 0..3
    const int h    = blockIdx.y;
    const int qb   = blockIdx.x;
    const int w16  = w * 16;

    const __half* Qg = Q + ((size_t)h * S_LEN + (size_t)qb * BQ) * DKH;
    const __half* Kg = K + (size_t)h * S_LEN * DKH;
    const __half* Vg = V + (size_t)h * S_LEN * DKH;

    const int crow = tid >> 3;            // 0..63
    const int cseg = (tid & 7) * 8;       // halves offset

    auto issue_kv = [&](int kb, int bb) {
        const size_t goff = (size_t)(kb * BKC + crow) * DKH + cseg;
        cpa16(sK + (unsigned)(bb * KVBUF + crow * LH + cseg) * 2u, Kg + goff);
        cpa16(sV + (unsigned)(bb * KVBUF + crow * LH + cseg) * 2u, Vg + goff);
    };

    // ---- prologue: Q tile + K/V chunk 0 ----
#pragma unroll
    for (int p = 0; p < 4; p++) {
        const int f   = tid + p * 512;
        const int row = f >> 3;
        const int seg = (f & 7) * 8;
        cpa16(sQP + (unsigned)(row * LH + seg) * 2u, Qg + (size_t)row * DKH + seg);
    }
    issue_kv(0, 0);
    CP_COMMIT();
    CP_WAIT0();
    __syncthreads();

    const int afrow = ((lane >> 3) & 1) * 8 + (lane & 7);
    const int afcol = (lane >> 4) * 8;
    const unsigned klane = (unsigned)((lane & 7) * LH + (lane >> 3) * 8) * 2u;
    const unsigned vlane = (unsigned)((((lane >> 3) & 1) * 8 + (lane & 7)) * LH
                                      + (lane >> 4) * 8) * 2u;
    const unsigned qbase = sQP + (unsigned)((w16 + afrow) * LH + afcol) * 2u;

    unsigned qa[4][4];
#pragma unroll
    for (int ks = 0; ks < 4; ks++)
        ldsm_x4(qbase + (unsigned)(ks * 16) * 2u,
                qa[ks][0], qa[ks][1], qa[ks][2], qa[ks][3]);

    float m0 = -INFINITY, m1 = -INFINITY, l0 = 0.f, l1 = 0.f;
    float o[8][4];
#pragma unroll
    for (int nt = 0; nt < 8; nt++)
#pragma unroll
        for (int j = 0; j < 4; j++) o[nt][j] = 0.f;

    const int row0 = qb * BQ + w16 + g;
    const int row1 = row0 + 8;
    const unsigned long long* mb0p = mbits + (size_t)row0 * 64;
    const unsigned long long* mb1p = mbits + (size_t)row1 * 64;

    for (int kb = 0; kb < S_LEN / BKC; kb++) {
        CP_WAIT0();
        __syncthreads();

        const unsigned long long b0 = mb0p[kb] >> (2 * tig);
        const unsigned long long b1 = mb1p[kb] >> (2 * tig);

        if (kb + 1 < S_LEN / BKC) { issue_kv(kb + 1, (kb + 1) & 1); CP_COMMIT(); }

        const unsigned kbase = sK + (unsigned)((kb & 1) * KVBUF) * 2u + klane;
        const unsigned vbase = sV + (unsigned)((kb & 1) * KVBUF) * 2u + vlane;

        // ---- S = Q * K^T ----
        float s[8][4];
#pragma unroll
        for (int nt = 0; nt < 8; nt++) {
#pragma unroll
            for (int j = 0; j < 4; j++) s[nt][j] = 0.f;
            const unsigned bnt = kbase + (unsigned)(nt * 8 * LH) * 2u;
            unsigned r0, r1, r2, r3;
            ldsm_x4(bnt, r0, r1, r2, r3);
            mma_f16(s[nt], qa[0][0], qa[0][1], qa[0][2], qa[0][3], r0, r1);
            mma_f16(s[nt], qa[1][0], qa[1][1], qa[1][2], qa[1][3], r2, r3);
            ldsm_x4(bnt + 64u, r0, r1, r2, r3);
            mma_f16(s[nt], qa[2][0], qa[2][1], qa[2][2], qa[2][3], r0, r1);
            mma_f16(s[nt], qa[3][0], qa[3][1], qa[3][2], qa[3][3], r2, r3);
        }

        // ---- mask + online softmax (exp2 domain) ----
        float mx0 = -INFINITY, mx1 = -INFINITY;
#pragma unroll
        for (int nt = 0; nt < 8; nt++) {
            s[nt][0] = fmaf(s[nt][0], SCALE2, ((b0 >> (nt * 8    )) & 1ull) ? -1e9f : 0.f);
            s[nt][1] = fmaf(s[nt][1], SCALE2, ((b0 >> (nt * 8 + 1)) & 1ull) ? -1e9f : 0.f);
            s[nt][2] = fmaf(s[nt][2], SCALE2, ((b1 >> (nt * 8    )) & 1ull) ? -1e9f : 0.f);
            s[nt][3] = fmaf(s[nt][3], SCALE2, ((b1 >> (nt * 8 + 1)) & 1ull) ? -1e9f : 0.f);
            mx0 = fmaxf(mx0, fmaxf(s[nt][0], s[nt][1]));
            mx1 = fmaxf(mx1, fmaxf(s[nt][2], s[nt][3]));
        }
        mx0 = fmaxf(mx0, __shfl_xor_sync(0xffffffffu, mx0, 1));
        mx0 = fmaxf(mx0, __shfl_xor_sync(0xffffffffu, mx0, 2));
        mx1 = fmaxf(mx1, __shfl_xor_sync(0xffffffffu, mx1, 1));
        mx1 = fmaxf(mx1, __shfl_xor_sync(0xffffffffu, mx1, 2));

        const float mn0 = fmaxf(m0, mx0), mn1 = fmaxf(m1, mx1);
        const float sc0 = ex2f(m0 - mn0), sc1 = ex2f(m1 - mn1);
        m0 = mn0; m1 = mn1;

        float rs0 = 0.f, rs1 = 0.f;
#pragma unroll
        for (int nt = 0; nt < 8; nt++) {
            const float p0 = ex2f(s[nt][0] - mn0);
            const float p1 = ex2f(s[nt][1] - mn0);
            const float p2 = ex2f(s[nt][2] - mn1);
            const float p3 = ex2f(s[nt][3] - mn1);
            rs0 += p0 + p1;
            rs1 += p2 + p3;
            *(__half2*)&QPs[(w16 + g)     * LH + nt * 8 + 2 * tig] = __floats2half2_rn(p0, p1);
            *(__half2*)&QPs[(w16 + g + 8) * LH + nt * 8 + 2 * tig] = __floats2half2_rn(p2, p3);
            o[nt][0] *= sc0; o[nt][1] *= sc0;
            o[nt][2] *= sc1; o[nt][3] *= sc1;
        }
        rs0 += __shfl_xor_sync(0xffffffffu, rs0, 1);
        rs0 += __shfl_xor_sync(0xffffffffu, rs0, 2);
        rs1 += __shfl_xor_sync(0xffffffffu, rs1, 1);
        rs1 += __shfl_xor_sync(0xffffffffu, rs1, 2);
        l0 = l0 * sc0 + rs0;
        l1 = l1 * sc1 + rs1;

        __syncwarp();   // P visible within warp (exclusive row ownership)

        // ---- O += P * V ----
        const unsigned pbase = sQP + (unsigned)((w16 + afrow) * LH + afcol) * 2u;
#pragma unroll
        for (int kc = 0; kc < 4; kc++) {
            unsigned pa0, pa1, pa2, pa3;
            ldsm_x4(pbase + (unsigned)(kc * 16) * 2u, pa0, pa1, pa2, pa3);
            const unsigned vkc = vbase + (unsigned)(kc * 16 * LH) * 2u;
#pragma unroll
            for (int ntp = 0; ntp < 4; ntp++) {
                unsigned r0, r1, r2, r3;
                ldsm_x4_trans(vkc + (unsigned)(ntp * 16) * 2u, r0, r1, r2, r3);
                mma_f16(o[2 * ntp],     pa0, pa1, pa2, pa3, r0, r1);
                mma_f16(o[2 * ntp + 1], pa0, pa1, pa2, pa3, r2, r3);
            }
        }
    }

    // ---- normalize + write AttnOut[token][h*64 + d] (fp16) ----
    const float inv0 = 1.0f / l0, inv1 = 1.0f / l1;
    __half* O0 = O + (size_t)row0 * DMODEL + h * DKH + 2 * tig;
    __half* O1 = O + (size_t)row1 * DMODEL + h * DKH + 2 * tig;
#pragma unroll
    for (int nt = 0; nt < 8; nt++) {
        *(__half2*)(O0 + nt * 8) = __floats2half2_rn(o[nt][0] * inv0, o[nt][1] * inv0);
        *(__half2*)(O1 + nt * 8) = __floats2half2_rn(o[nt][2] * inv1, o[nt][3] * inv1);
    }
}

// ============================================================================
extern "C" void kernel_launch(void* const* d_in, const int* in_sizes, int n_in,
                              void* d_out, int out_size)
{
    const float* x       = (const float*)d_in[0];
    const int*   mask    = (const int*)  d_in[1];
    const float* wq_w    = (const float*)d_in[2];
    const float* wq_b    = (const float*)d_in[3];
    const float* wk_w    = (const float*)d_in[4];
    const float* wk_b    = (const float*)d_in[5];
    const float* wv_w    = (const float*)d_in[6];
    const float* wv_b    = (const float*)d_in[7];
    const float* dense_w = (const float*)d_in[8];
    const float* dense_b = (const float*)d_in[9];
    float* out = (float*)d_out;

    __half *xh, *Wq, *Wk, *Wv, *Wd, *Qp, *Kp, *Vp, *AOp;
    unsigned long long* MBp;
    cudaGetSymbolAddress((void**)&xh,  g_xh);
    cudaGetSymbolAddress((void**)&Wq,  g_Wq);
    cudaGetSymbolAddress((void**)&Wk,  g_Wk);
    cudaGetSymbolAddress((void**)&Wv,  g_Wv);
    cudaGetSymbolAddress((void**)&Wd,  g_Wd);
    cudaGetSymbolAddress((void**)&Qp,  g_Qh);
    cudaGetSymbolAddress((void**)&Kp,  g_Kh);
    cudaGetSymbolAddress((void**)&Vp,  g_Vh);
    cudaGetSymbolAddress((void**)&AOp, g_AOh);
    cudaGetSymbolAddress((void**)&MBp, g_MB);

    cudaFuncSetAttribute(attn_tc_kernel,
                         cudaFuncAttributeMaxDynamicSharedMemorySize,
                         ATTN_SMEM_BYTES);
    cudaFuncSetAttribute(qkv_gemm_kernel,
                         cudaFuncAttributeMaxDynamicSharedMemorySize,
                         GEMM_SMEM_BYTES);
    cudaFuncSetAttribute(dense_gemm_kernel,
                         cudaFuncAttributeMaxDynamicSharedMemorySize,
                         GEMM_SMEM_BYTES);

    // 0) Convert x + weights to fp16; bit-pack the mask
    f2h_kernel<<<(S_LEN * IN_DIM / 4 + 255) / 256, 256>>>(x, xh, S_LEN * IN_DIM / 4);
    f2h_kernel<<<(DMODEL * IN_DIM / 4 + 255) / 256, 256>>>(wq_w, Wq, DMODEL * IN_DIM / 4);
    f2h_kernel<<<(DMODEL * IN_DIM / 4 + 255) / 256, 256>>>(wk_w, Wk, DMODEL * IN_DIM / 4);
    f2h_kernel<<<(DMODEL * IN_DIM / 4 + 255) / 256, 256>>>(wv_w, Wv, DMODEL * IN_DIM / 4);
    f2h_kernel<<<(DMODEL * DMODEL / 4 + 255) / 256, 256>>>(dense_w, Wd, DMODEL * DMODEL / 4);
    pack_mask_kernel<<<(S_LEN * 64 * 32) / 256, 256>>>(mask, MBp);

    // 1) Fused QKV projections (fp16 mma GEMM, fp16 outputs)
    qkv_gemm_kernel<<<dim3(12, S_LEN / 128), 256, GEMM_SMEM_BYTES>>>(
        xh, Wq, wq_b, Wk, wk_b, Wv, wv_b, Qp, Kp, Vp);

    // 2) Masked flash attention (fp16 m16n8k16 mma), fp16 output
    attn_tc_kernel<<<dim3(S_LEN / BQ, NHEAD), 512, ATTN_SMEM_BYTES>>>(
        Qp, Kp, Vp, MBp, AOp);

    // 3) Dense output projection (fp16 mma GEMM, fp32 output)
    dense_gemm_kernel<<<dim3(DMODEL / 128, S_LEN / 128), 256, GEMM_SMEM_BYTES>>>(
        AOp, Wd, dense_b, out);
}